// round 13
// baseline (speedup 1.0000x reference)
#include <cuda_runtime.h>
#include <cuda_fp16.h>
#include <cstdint>

// SoftmaxRefMatcher: persistent mma.sync fp16 GEMM + fused fixed-shift softmax.
// R13: revert to R11 math; triple-buffered B (prefetch depth 2, ONE bar/tile);
// merged single prep launch. BW=8, C=64, N=256, HW=65536 -> B=2, NW=6.

#define CK     64
#define NKP    256
#define HW     65536
#define NW     6
#define TPX    128
#define NTILE  512
#define NGRP   12
#define CPG    49
#define NCTA   (NGRP * CPG)     // 588
#define NPART  (CPG * 2)

__device__ __align__(256) __half g_A[NW * NKP * CK];
__device__ __align__(256) __half g_B[2 * HW * CK];
__device__ __align__(256) float4 g_part[NW * NKP * NPART];   // {s,u,v,pad}

__device__ __forceinline__ uint32_t smem_u32(const void* p) {
    uint32_t a;
    asm("{ .reg .u64 t; cvta.to.shared.u64 t, %1; cvt.u32.u64 %0, t; }" : "=r"(a) : "l"(p));
    return a;
}
#define LDSM4(R, addr) \
    asm volatile("ldmatrix.sync.aligned.m8n8.x4.shared.b16 {%0,%1,%2,%3}, [%4];" \
        : "=r"((R)[0]), "=r"((R)[1]), "=r"((R)[2]), "=r"((R)[3]) : "r"(addr))
#define MMA16816(D, A, b0, b1) \
    asm volatile("mma.sync.aligned.m16n8k16.row.col.f32.f16.f16.f32 " \
        "{%0,%1,%2,%3}, {%4,%5,%6,%7}, {%8,%9}, {%0,%1,%2,%3};" \
        : "+f"((D)[0]), "+f"((D)[1]), "+f"((D)[2]), "+f"((D)[3]) \
        : "r"((A)[0]), "r"((A)[1]), "r"((A)[2]), "r"((A)[3]), "r"(b0), "r"(b1))
#define CP16(dst, src) \
    asm volatile("cp.async.cg.shared.global [%0], [%1], 16;" :: "r"(dst), "l"(src))
#define CP_COMMIT() asm volatile("cp.async.commit_group;" ::: "memory")
#define CP_WAIT1()  asm volatile("cp.async.wait_group 1;" ::: "memory")
#define BARH(id)    asm volatile("bar.sync %0, 128;" :: "r"(id) : "memory")

// ---------------------------------------------------------------- merged prep
__global__ __launch_bounds__(128) void k_prep(const float* __restrict__ kd,
                                              const float* __restrict__ dd) {
    int bid = blockIdx.x, tid = threadIdx.x;
    if (bid < 1024) {
        // ---- src: normalize + fp16 + transpose to [pixel][channel] ----
        __shared__ uint32_t sH[128 * 33];
        int pidx = bid * 128 + tid;
        int b = pidx >> 16;
        const float* src = dd + (size_t)(b * 4) * CK * HW + (pidx & (HW - 1));
        float v[CK]; float ss = 0.f;
        #pragma unroll
        for (int c = 0; c < CK; c++) { v[c] = src[(size_t)c * HW]; ss += v[c] * v[c]; }
        float inv = 1.f / fmaxf(sqrtf(ss), 1e-12f);
        #pragma unroll
        for (int j = 0; j < 32; j++) {
            __half h0 = __float2half(v[2 * j] * inv);
            __half h1 = __float2half(v[2 * j + 1] * inv);
            sH[tid * 33 + j] = (uint32_t)__half_as_ushort(h0) | ((uint32_t)__half_as_ushort(h1) << 16);
        }
        __syncthreads();
        uint32_t* oH = reinterpret_cast<uint32_t*>(g_B) + (size_t)bid * 128 * 32;
        #pragma unroll
        for (int i = 0; i < 32; i++) {
            int u = tid + i * 128;
            int mm = u >> 5, j = u & 31;
            oH[u] = sH[mm * 33 + j];
        }
    } else {
        // ---- tgt: normalize + fp16, layout [w][n][c] ----
        int idx = bid - 1024;               // 0..11
        int w = idx >> 1;
        int n = (idx & 1) * 128 + tid;
        int f = (w / 3) * 4 + (w % 3) + 1;
        const float* src = kd + f * CK * NKP + n;
        float v[CK]; float ss = 0.f;
        #pragma unroll
        for (int c = 0; c < CK; c++) { v[c] = src[c * NKP]; ss += v[c] * v[c]; }
        float inv = 1.f / fmaxf(sqrtf(ss), 1e-12f);
        int base = (w * NKP + n) * CK;
        #pragma unroll
        for (int c = 0; c < CK; c++) g_A[base + c] = __float2half(v[c] * inv);
    }
}

// ---------------------------------------------------------------- persistent GEMM + softmax
// smem: A 16K | half0 {3 bufs x 8K} | half1 {24K} = 64K
#define SM_A 0
#define SM_B(half, buf) (16384 + (half) * 24576 + (buf) * 8192)
#define SM_TOT 65536

__global__ void __launch_bounds__(256, 2) k_gemm() {
    extern __shared__ char smem[];
    uint32_t sb = smem_u32(smem);
    int tid = threadIdx.x;
    int cta = blockIdx.x;
    int grp = cta % NGRP, j = cta / NGRP;
    int w = grp >> 1, kh = grp & 1, b = w / 3;
    int t0 = (j * NTILE) / CPG, t1 = ((j + 1) * NTILE) / CPG;

    int lane = tid & 31, wid = tid >> 5;
    int half = tid >> 7;
    int h = tid & 127;
    int n0 = half * 64;
    int barid = 1 + half;

    // ---- prefetch A (once, whole CTA) ----
    {
        const __half* gA = g_A + (size_t)(w * NKP + kh * 128) * CK;
        #pragma unroll
        for (int i = 0; i < 4; i++) {
            int ch = tid + i * 256;
            int row = ch >> 3, c = ch & 7;
            const __half* src = gA + row * CK + c * 8;
            uint32_t dst = sb + SM_A + row * 128 + (((c ^ (row & 7))) << 4);
            CP16(dst, (const void*)src);
        }
    }
    const __half* gB = g_B + (size_t)b * HW * CK;
    auto prefB = [&](int buf, int t) {
        #pragma unroll
        for (int i = 0; i < 4; i++) {
            int ch = h + i * 128;
            int row = ch >> 3, c = ch & 7;
            const __half* src = gB + (size_t)(t * TPX + n0 + row) * CK + c * 8;
            uint32_t dst = sb + SM_B(half, buf) + row * 128 + (((c ^ (row & 7))) << 4);
            CP16(dst, (const void*)src);
        }
    };
    // prologue: prefetch t0 (with A) and t0+1, depth 2
    prefB(0, t0);
    CP_COMMIT();
    if (t0 + 1 < t1) { prefB(1, t0 + 1); }
    CP_COMMIT();

    // ---- fragment addressing ----
    int m0 = (wid & 3) * 32;
    int aRow = (lane & 7) + ((lane >> 3) & 1) * 8;
    int aCh  = (lane >> 4) & 1;
    int bRow = (lane & 7) + ((lane >> 4) & 1) * 8;
    int bCh  = (lane >> 3) & 1;
    int rA0 = m0 + aRow, rA1 = rA0 + 16;
    uint32_t aB0 = sb + SM_A + rA0 * 128, aB1 = sb + SM_A + rA1 * 128;
    int xA0 = rA0 & 7, xA1 = rA1 & 7;
    uint32_t bOff[4]; int xB[4];
    #pragma unroll
    for (int q = 0; q < 4; q++) {
        int rB = q * 16 + bRow;
        bOff[q] = rB * 128; xB[q] = rB & 7;
    }
    int g = lane >> 2, t4 = lane & 3;
    const float K1 = 144.2695041f;                 // 100 * log2(e)
    float t4f2 = (float)(n0 + t4 * 2);

    // cross-tile accumulators
    float sA[2][2] = {{0.f,0.f},{0.f,0.f}};
    float uA[2][2] = {{0.f,0.f},{0.f,0.f}};
    float vA[2][2] = {{0.f,0.f},{0.f,0.f}};

    int buf = 0;
    for (int t = t0; t < t1; t++) {
        CP_WAIT1();                                 // buf for tile t arrived (this thread)
        if (t == t0) __syncthreads();               // A + B(t0) visibility (cross-half A writers)
        else BARH(barid);                           // all threads' loads visible; prev reads done
        // safe now to overwrite buf (t+2)%3 — its last reader was mainloop(t-1)
        if (t + 2 < t1) { prefB((buf + 2) % 3, t + 2); CP_COMMIT(); }

        float acc[2][8][4];
        #pragma unroll
        for (int i = 0; i < 2; i++)
            #pragma unroll
            for (int nt = 0; nt < 8; nt++)
                #pragma unroll
                for (int q = 0; q < 4; q++) acc[i][nt][q] = 0.f;

        uint32_t bB = sb + SM_B(half, buf);
        #pragma unroll
        for (int ks = 0; ks < 4; ks++) {
            uint32_t Af0[4], Af1[4], Bf[4][4];
            int chA = aCh + 2 * ks;
            int chB = bCh + 2 * ks;
            LDSM4(Af0, aB0 + ((chA ^ xA0) << 4));
            LDSM4(Af1, aB1 + ((chA ^ xA1) << 4));
            #pragma unroll
            for (int q = 0; q < 4; q++) LDSM4(Bf[q], bB + bOff[q] + ((chB ^ xB[q]) << 4));
            #pragma unroll
            for (int nt = 0; nt < 8; nt++) {
                uint32_t b0 = Bf[nt >> 1][(nt & 1) * 2];
                uint32_t b1 = Bf[nt >> 1][(nt & 1) * 2 + 1];
                MMA16816(acc[0][nt], Af0, b0, b1);
                MMA16816(acc[1][nt], Af1, b0, b1);
            }
        }

        // ---- epilogue (reg-private; no barrier needed) ----
        float uoff = (float)((t & 1) * 128);
        float vt = (float)(t >> 1);
        #pragma unroll
        for (int mt = 0; mt < 2; mt++) {
            float s0 = 0.f, m0f = 0.f, o0 = 0.f;
            float s1 = 0.f, m1f = 0.f, o1 = 0.f;
            #pragma unroll
            for (int nt = 0; nt < 8; nt++) {
                float ntf = (float)nt;
                float e0, e1, e2, e3;
                asm("ex2.approx.ftz.f32 %0, %1;" : "=f"(e0) : "f"(fmaf(acc[mt][nt][0], K1, -K1)));
                asm("ex2.approx.ftz.f32 %0, %1;" : "=f"(e1) : "f"(fmaf(acc[mt][nt][1], K1, -K1)));
                asm("ex2.approx.ftz.f32 %0, %1;" : "=f"(e2) : "f"(fmaf(acc[mt][nt][2], K1, -K1)));
                asm("ex2.approx.ftz.f32 %0, %1;" : "=f"(e3) : "f"(fmaf(acc[mt][nt][3], K1, -K1)));
                float p0 = e0 + e1, p1 = e2 + e3;
                s0 += p0;  m0f = fmaf(ntf, p0, m0f);  o0 += e1;
                s1 += p1;  m1f = fmaf(ntf, p1, m1f);  o1 += e3;
            }
            float u0 = fmaf(8.f, m0f, o0); u0 = fmaf(t4f2 + uoff, s0, u0);
            float u1 = fmaf(8.f, m1f, o1); u1 = fmaf(t4f2 + uoff, s1, u1);
            sA[mt][0] += s0;  uA[mt][0] += u0;  vA[mt][0] = fmaf(vt, s0, vA[mt][0]);
            sA[mt][1] += s1;  uA[mt][1] += u1;  vA[mt][1] = fmaf(vt, s1, vA[mt][1]);
        }
        buf = (buf + 1) % 3;
    }

    // ---- single final reduce across the 4 t4-lanes + store ----
    #pragma unroll
    for (int mt = 0; mt < 2; mt++) {
        #pragma unroll
        for (int sr = 0; sr < 2; sr++) {
            float s = sA[mt][sr], u = uA[mt][sr], v = vA[mt][sr];
            #pragma unroll
            for (int d = 1; d <= 2; d <<= 1) {
                s += __shfl_xor_sync(0xFFFFFFFF, s, d);
                u += __shfl_xor_sync(0xFFFFFFFF, u, d);
                v += __shfl_xor_sync(0xFFFFFFFF, v, d);
            }
            if (t4 == 0) {
                int r = m0 + mt * 16 + sr * 8 + g;
                size_t row = (size_t)w * NKP + kh * 128 + r;
                g_part[row * NPART + j * 2 + half] = make_float4(s, u, v, 0.f);
            }
        }
    }
}

// ---------------------------------------------------------------- reduce + tail merged
__global__ __launch_bounds__(256) void k_finish(const float* __restrict__ scores,
                                                float* __restrict__ out) {
    if (blockIdx.x < 192) {
        int row = blockIdx.x * 8 + (threadIdx.x >> 5);
        int lane = threadIdx.x & 31;
        const float4* p = g_part + (size_t)row * NPART;
        float s = 0.f, u = 0.f, v = 0.f;
        #pragma unroll
        for (int i = 0; i < 4; i++) {
            int idx = lane + i * 32;
            if (idx < NPART) {
                float4 q = p[idx];
                s += q.x; u += q.y; v += q.z;
            }
        }
        #pragma unroll
        for (int d = 16; d > 0; d >>= 1) {
            s += __shfl_xor_sync(0xFFFFFFFF, s, d);
            u += __shfl_xor_sync(0xFFFFFFFF, u, d);
            v += __shfl_xor_sync(0xFFFFFFFF, v, d);
        }
        if (lane == 0) {
            float inv = 1.f / s;
            out[row * 2 + 0] = u * inv;
            out[row * 2 + 1] = v * inv;
        }
    } else {
        int w = blockIdx.x - 192, n = threadIdx.x;
        int f = (w / 3) * 4 + (w % 3) + 1;
        out[3072 + w * NKP + n] = scores[f * NKP + n];
        if (n == 0) {
            out[4608 + w] = (float)f;
            out[4614 + w] = (float)((w / 3) * 4);
        }
    }
}

extern "C" void kernel_launch(void* const* d_in, const int* in_sizes, int n_in,
                              void* d_out, int out_size) {
    (void)in_sizes; (void)n_in; (void)out_size;
    const float* scores = (const float*)d_in[0];
    const float* kd     = (const float*)d_in[1];
    const float* dd     = (const float*)d_in[2];
    float* out = (float*)d_out;

    cudaFuncSetAttribute(k_gemm, cudaFuncAttributeMaxDynamicSharedMemorySize, SM_TOT);

    k_prep<<<1036, 128>>>(kd, dd);          // launch 0
    k_gemm<<<NCTA, 256, SM_TOT>>>();        // launch 1
    k_finish<<<198, 256>>>(scores, out);    // launch 2
}

// round 14
// speedup vs baseline: 1.1964x; 1.1964x over previous
#include <cuda_runtime.h>
#include <cuda_fp16.h>
#include <cstdint>

// SoftmaxRefMatcher: persistent mma.sync fp16 GEMM + fused fixed-shift softmax.
// R14: exact R11 pipeline (proven 60us) + k_finish fused into k_gemm tail via
// threadfence-reduction (last CTA per group reduces; bit-identical math).
// BW=8, C=64, N=256, HW=65536, WINDOW=4 -> B=2, NW=6, 12 (w,kh) groups.

#define CK     64
#define NKP    256
#define HW     65536
#define NW     6
#define TPX    128
#define NTILE  512
#define NGRP   12
#define CPG    49
#define NCTA   (NGRP * CPG)     // 588
#define NPART  (CPG * 2)        // partials per row

__device__ __align__(256) __half g_A[NW * NKP * CK];
__device__ __align__(256) __half g_B[2 * HW * CK];
__device__ __align__(256) float4 g_part[NW * NKP * NPART];   // {s,u,v,pad}
__device__ int g_cnt[NGRP];

__device__ __forceinline__ uint32_t smem_u32(const void* p) {
    uint32_t a;
    asm("{ .reg .u64 t; cvta.to.shared.u64 t, %1; cvt.u32.u64 %0, t; }" : "=r"(a) : "l"(p));
    return a;
}
#define LDSM4(R, addr) \
    asm volatile("ldmatrix.sync.aligned.m8n8.x4.shared.b16 {%0,%1,%2,%3}, [%4];" \
        : "=r"((R)[0]), "=r"((R)[1]), "=r"((R)[2]), "=r"((R)[3]) : "r"(addr))
#define MMA16816(D, A, b0, b1) \
    asm volatile("mma.sync.aligned.m16n8k16.row.col.f32.f16.f16.f32 " \
        "{%0,%1,%2,%3}, {%4,%5,%6,%7}, {%8,%9}, {%0,%1,%2,%3};" \
        : "+f"((D)[0]), "+f"((D)[1]), "+f"((D)[2]), "+f"((D)[3]) \
        : "r"((A)[0]), "r"((A)[1]), "r"((A)[2]), "r"((A)[3]), "r"(b0), "r"(b1))
#define CP16(dst, src) \
    asm volatile("cp.async.cg.shared.global [%0], [%1], 16;" :: "r"(dst), "l"(src))
#define CP_COMMIT() asm volatile("cp.async.commit_group;" ::: "memory")
#define CP_WAIT1()  asm volatile("cp.async.wait_group 1;" ::: "memory")
#define BARH(id)    asm volatile("bar.sync %0, 128;" :: "r"(id) : "memory")

// ---------------------------------------------------------------- tgt prep (A: fp16) + counter reset
__global__ __launch_bounds__(128) void k_prep_tgt(const float* __restrict__ kd) {
    int idx = blockIdx.x;                   // 0..11
    int tid = threadIdx.x;
    if (idx == 0 && tid < NGRP) g_cnt[tid] = 0;
    int w = idx >> 1;
    int n = (idx & 1) * 128 + tid;
    int f = (w / 3) * 4 + (w % 3) + 1;
    const float* src = kd + f * CK * NKP + n;
    float v[CK]; float ss = 0.f;
    #pragma unroll
    for (int c = 0; c < CK; c++) { v[c] = src[c * NKP]; ss += v[c] * v[c]; }
    float inv = 1.f / fmaxf(sqrtf(ss), 1e-12f);
    int base = (w * NKP + n) * CK;
    #pragma unroll
    for (int c = 0; c < CK; c++) g_A[base + c] = __float2half(v[c] * inv);
}

// ---------------------------------------------------------------- src prep (B: fp16, transposed)
__global__ __launch_bounds__(128) void k_prep_src(const float* __restrict__ dd, int blk0) {
    __shared__ uint32_t sH[128 * 33];
    int bid = blockIdx.x + blk0;
    int tid = threadIdx.x;
    int pidx = bid * 128 + tid;
    int b = pidx >> 16;
    const float* src = dd + (size_t)(b * 4) * CK * HW + (pidx & (HW - 1));
    float v[CK]; float ss = 0.f;
    #pragma unroll
    for (int c = 0; c < CK; c++) { v[c] = src[(size_t)c * HW]; ss += v[c] * v[c]; }
    float inv = 1.f / fmaxf(sqrtf(ss), 1e-12f);
    #pragma unroll
    for (int j = 0; j < 32; j++) {
        __half h0 = __float2half(v[2 * j] * inv);
        __half h1 = __float2half(v[2 * j + 1] * inv);
        sH[tid * 33 + j] = (uint32_t)__half_as_ushort(h0) | ((uint32_t)__half_as_ushort(h1) << 16);
    }
    __syncthreads();
    uint32_t* oH = reinterpret_cast<uint32_t*>(g_B) + (size_t)bid * 128 * 32;
    #pragma unroll
    for (int i = 0; i < 32; i++) {
        int u = tid + i * 128;
        int mm = u >> 5, j = u & 31;
        oH[u] = sH[mm * 33 + j];
    }
}

// ---------------------------------------------------------------- persistent GEMM + softmax + tail
// smem: A 16K | half0 {buf0 8K, buf1 8K} | half1 {16K} = 48K
#define SM_A 0
#define SM_B(half, buf) (16384 + (half) * 16384 + (buf) * 8192)
#define SM_TOT 49152

__global__ void __launch_bounds__(256, 2) k_gemm(const float* __restrict__ scores,
                                                 float* __restrict__ out) {
    extern __shared__ char smem[];
    uint32_t sb = smem_u32(smem);
    int tid = threadIdx.x;
    int cta = blockIdx.x;
    int grp = cta % NGRP, j = cta / NGRP;
    int w = grp >> 1, kh = grp & 1, b = w / 3;
    int t0 = (j * NTILE) / CPG, t1 = ((j + 1) * NTILE) / CPG;

    int lane = tid & 31, wid = tid >> 5;
    int half = tid >> 7;
    int h = tid & 127;
    int n0 = half * 64;
    int barid = 1 + half;

    // ---- prefetch A (once, whole CTA) ----
    {
        const __half* gA = g_A + (size_t)(w * NKP + kh * 128) * CK;
        #pragma unroll
        for (int i = 0; i < 4; i++) {
            int ch = tid + i * 256;
            int row = ch >> 3, c = ch & 7;
            const __half* src = gA + row * CK + c * 8;
            uint32_t dst = sb + SM_A + row * 128 + (((c ^ (row & 7))) << 4);
            CP16(dst, (const void*)src);
        }
    }
    const __half* gB = g_B + (size_t)b * HW * CK;
    auto prefB = [&](int buf, int t) {
        #pragma unroll
        for (int i = 0; i < 4; i++) {
            int ch = h + i * 128;
            int row = ch >> 3, c = ch & 7;
            const __half* src = gB + (size_t)(t * TPX + n0 + row) * CK + c * 8;
            uint32_t dst = sb + SM_B(half, buf) + row * 128 + (((c ^ (row & 7))) << 4);
            CP16(dst, (const void*)src);
        }
    };
    prefB(0, t0);
    CP_COMMIT();

    // ---- fragment addressing ----
    int m0 = (wid & 3) * 32;
    int aRow = (lane & 7) + ((lane >> 3) & 1) * 8;
    int aCh  = (lane >> 4) & 1;
    int bRow = (lane & 7) + ((lane >> 4) & 1) * 8;
    int bCh  = (lane >> 3) & 1;
    int rA0 = m0 + aRow, rA1 = rA0 + 16;
    uint32_t aB0 = sb + SM_A + rA0 * 128, aB1 = sb + SM_A + rA1 * 128;
    int xA0 = rA0 & 7, xA1 = rA1 & 7;
    uint32_t bOff[4]; int xB[4];
    #pragma unroll
    for (int q = 0; q < 4; q++) {
        int rB = q * 16 + bRow;
        bOff[q] = rB * 128; xB[q] = rB & 7;
    }
    int g = lane >> 2, t4 = lane & 3;
    const float K1 = 144.2695041f;                 // 100 * log2(e)
    float t4f2 = (float)(n0 + t4 * 2);

    // cross-tile accumulators
    float sA[2][2] = {{0.f,0.f},{0.f,0.f}};
    float uA[2][2] = {{0.f,0.f},{0.f,0.f}};
    float vA[2][2] = {{0.f,0.f},{0.f,0.f}};

    int buf = 0;
    for (int t = t0; t < t1; t++) {
        if (t + 1 < t1) prefB(buf ^ 1, t + 1);
        CP_COMMIT();
        CP_WAIT1();
        if (t == t0) __syncthreads();              // A + B(t0) visibility
        else BARH(barid);                          // B(t) visibility within half

        float acc[2][8][4];
        #pragma unroll
        for (int i = 0; i < 2; i++)
            #pragma unroll
            for (int nt = 0; nt < 8; nt++)
                #pragma unroll
                for (int q = 0; q < 4; q++) acc[i][nt][q] = 0.f;

        uint32_t bB = sb + SM_B(half, buf);
        #pragma unroll
        for (int ks = 0; ks < 4; ks++) {
            uint32_t Af0[4], Af1[4], Bf[4][4];
            int chA = aCh + 2 * ks;
            int chB = bCh + 2 * ks;
            LDSM4(Af0, aB0 + ((chA ^ xA0) << 4));
            LDSM4(Af1, aB1 + ((chA ^ xA1) << 4));
            #pragma unroll
            for (int q = 0; q < 4; q++) LDSM4(Bf[q], bB + bOff[q] + ((chB ^ xB[q]) << 4));
            #pragma unroll
            for (int nt = 0; nt < 8; nt++) {
                uint32_t b0 = Bf[nt >> 1][(nt & 1) * 2];
                uint32_t b1 = Bf[nt >> 1][(nt & 1) * 2 + 1];
                MMA16816(acc[0][nt], Af0, b0, b1);
                MMA16816(acc[1][nt], Af1, b0, b1);
            }
        }

        BARH(barid);       // release buf (epilogue is reg-private)

        // ---- epilogue: per-tile (s,u) then fold into cross-tile accumulators ----
        float uoff = (float)((t & 1) * 128);
        float vt = (float)(t >> 1);
        #pragma unroll
        for (int mt = 0; mt < 2; mt++) {
            float s0 = 0.f, m0f = 0.f, o0 = 0.f;
            float s1 = 0.f, m1f = 0.f, o1 = 0.f;
            #pragma unroll
            for (int nt = 0; nt < 8; nt++) {
                float ntf = (float)nt;
                float e0, e1, e2, e3;
                asm("ex2.approx.ftz.f32 %0, %1;" : "=f"(e0) : "f"(fmaf(acc[mt][nt][0], K1, -K1)));
                asm("ex2.approx.ftz.f32 %0, %1;" : "=f"(e1) : "f"(fmaf(acc[mt][nt][1], K1, -K1)));
                asm("ex2.approx.ftz.f32 %0, %1;" : "=f"(e2) : "f"(fmaf(acc[mt][nt][2], K1, -K1)));
                asm("ex2.approx.ftz.f32 %0, %1;" : "=f"(e3) : "f"(fmaf(acc[mt][nt][3], K1, -K1)));
                float p0 = e0 + e1, p1 = e2 + e3;
                s0 += p0;  m0f = fmaf(ntf, p0, m0f);  o0 += e1;
                s1 += p1;  m1f = fmaf(ntf, p1, m1f);  o1 += e3;
            }
            float u0 = fmaf(8.f, m0f, o0); u0 = fmaf(t4f2 + uoff, s0, u0);
            float u1 = fmaf(8.f, m1f, o1); u1 = fmaf(t4f2 + uoff, s1, u1);
            sA[mt][0] += s0;  uA[mt][0] += u0;  vA[mt][0] = fmaf(vt, s0, vA[mt][0]);
            sA[mt][1] += s1;  uA[mt][1] += u1;  vA[mt][1] = fmaf(vt, s1, vA[mt][1]);
        }
        buf ^= 1;
    }

    // ---- final per-warp reduce + partial store ----
    #pragma unroll
    for (int mt = 0; mt < 2; mt++) {
        #pragma unroll
        for (int sr = 0; sr < 2; sr++) {
            float s = sA[mt][sr], u = uA[mt][sr], v = vA[mt][sr];
            #pragma unroll
            for (int d = 1; d <= 2; d <<= 1) {
                s += __shfl_xor_sync(0xFFFFFFFF, s, d);
                u += __shfl_xor_sync(0xFFFFFFFF, u, d);
                v += __shfl_xor_sync(0xFFFFFFFF, v, d);
            }
            if (t4 == 0) {
                int r = m0 + mt * 16 + sr * 8 + g;
                size_t row = (size_t)w * NKP + kh * 128 + r;
                g_part[row * NPART + j * 2 + half] = make_float4(s, u, v, 0.f);
            }
        }
    }

    // ---- fused finish: last CTA of each group reduces its 128 rows ----
    __threadfence();
    __shared__ int amLast;
    if (tid == 0) amLast = (atomicAdd(&g_cnt[grp], 1) == CPG - 1) ? 1 : 0;
    __syncthreads();
    if (amLast) {
        int lane2 = tid & 31, wr = tid >> 5;           // 8 warps x 16 rows
        for (int k = 0; k < 16; k++) {
            size_t row = (size_t)w * NKP + kh * 128 + wr * 16 + k;
            const float4* p = g_part + row * NPART;
            float s = 0.f, u = 0.f, v = 0.f;
            #pragma unroll
            for (int i = 0; i < 4; i++) {
                int idx = lane2 + i * 32;
                if (idx < NPART) {
                    float4 q = __ldcg(p + idx);        // L1-bypass: other CTAs' stores
                    s += q.x; u += q.y; v += q.z;
                }
            }
            #pragma unroll
            for (int d = 16; d > 0; d >>= 1) {
                s += __shfl_xor_sync(0xFFFFFFFF, s, d);
                u += __shfl_xor_sync(0xFFFFFFFF, u, d);
                v += __shfl_xor_sync(0xFFFFFFFF, v, d);
            }
            if (lane2 == 0) {
                float inv = 1.f / s;
                out[row * 2 + 0] = u * inv;
                out[row * 2 + 1] = v * inv;
            }
        }
        // scores + ids tail (once per w, from the kh==0 group)
        if (kh == 0) {
            int f = (w / 3) * 4 + (w % 3) + 1;
            for (int n = tid; n < NKP; n += 256)
                out[3072 + w * NKP + n] = scores[f * NKP + n];
            if (tid == 0) {
                out[4608 + w] = (float)f;
                out[4614 + w] = (float)((w / 3) * 4);
            }
        }
    }
}

extern "C" void kernel_launch(void* const* d_in, const int* in_sizes, int n_in,
                              void* d_out, int out_size) {
    (void)in_sizes; (void)n_in; (void)out_size;
    const float* scores = (const float*)d_in[0];
    const float* kd     = (const float*)d_in[1];
    const float* dd     = (const float*)d_in[2];
    float* out = (float*)d_out;

    cudaFuncSetAttribute(k_gemm, cudaFuncAttributeMaxDynamicSharedMemorySize, SM_TOT);

    k_prep_tgt<<<NGRP, 128>>>(kd);          // launch 0 (also resets counters)
    k_prep_src<<<512, 128>>>(dd, 0);        // launch 1
    k_prep_src<<<512, 128>>>(dd, 512);      // launch 2
    k_gemm<<<NCTA, 256, SM_TOT>>>(scores, out);   // launch 3 (ncu lands here)
}

// round 16
// speedup vs baseline: 1.3355x; 1.1163x over previous
#include <cuda_runtime.h>
#include <cuda_fp16.h>
#include <cstdint>

// SoftmaxRefMatcher: persistent mma.sync fp16 GEMM + fused fixed-shift softmax.
// R15: k_gemm/k_finish reverted to R11 verbatim (proven 60us, gemm 46.4us).
// k_prep_src rewritten with smem-staged channels (95 -> ~25 regs, higher occ).
// BW=8, C=64, N=256, HW=65536, WINDOW=4 -> B=2, NW=6, 12 (w,kh) groups.

#define CK     64
#define NKP    256
#define HW     65536
#define NW     6
#define TPX    128
#define NTILE  512
#define NGRP   12
#define CPG    49
#define NCTA   (NGRP * CPG)     // 588
#define NPART  (CPG * 2)

__device__ __align__(256) __half g_A[NW * NKP * CK];
__device__ __align__(256) __half g_B[2 * HW * CK];
__device__ __align__(256) float4 g_part[NW * NKP * NPART];   // {s,u,v,pad}

__device__ __forceinline__ uint32_t smem_u32(const void* p) {
    uint32_t a;
    asm("{ .reg .u64 t; cvta.to.shared.u64 t, %1; cvt.u32.u64 %0, t; }" : "=r"(a) : "l"(p));
    return a;
}
#define LDSM4(R, addr) \
    asm volatile("ldmatrix.sync.aligned.m8n8.x4.shared.b16 {%0,%1,%2,%3}, [%4];" \
        : "=r"((R)[0]), "=r"((R)[1]), "=r"((R)[2]), "=r"((R)[3]) : "r"(addr))
#define MMA16816(D, A, b0, b1) \
    asm volatile("mma.sync.aligned.m16n8k16.row.col.f32.f16.f16.f32 " \
        "{%0,%1,%2,%3}, {%4,%5,%6,%7}, {%8,%9}, {%0,%1,%2,%3};" \
        : "+f"((D)[0]), "+f"((D)[1]), "+f"((D)[2]), "+f"((D)[3]) \
        : "r"((A)[0]), "r"((A)[1]), "r"((A)[2]), "r"((A)[3]), "r"(b0), "r"(b1))
#define CP16(dst, src) \
    asm volatile("cp.async.cg.shared.global [%0], [%1], 16;" :: "r"(dst), "l"(src))
#define CP_COMMIT() asm volatile("cp.async.commit_group;" ::: "memory")
#define CP_WAIT1()  asm volatile("cp.async.wait_group 1;" ::: "memory")
#define BARH(id)    asm volatile("bar.sync %0, 128;" :: "r"(id) : "memory")

// ---------------------------------------------------------------- tgt prep (A: fp16)
__global__ __launch_bounds__(128) void k_prep_tgt(const float* __restrict__ kd) {
    int idx = blockIdx.x;                   // 0..11
    int tid = threadIdx.x;
    int w = idx >> 1;
    int n = (idx & 1) * 128 + tid;
    int f = (w / 3) * 4 + (w % 3) + 1;
    const float* src = kd + f * CK * NKP + n;
    float v[CK]; float ss = 0.f;
    #pragma unroll
    for (int c = 0; c < CK; c++) { v[c] = src[c * NKP]; ss += v[c] * v[c]; }
    float inv = 1.f / fmaxf(sqrtf(ss), 1e-12f);
    int base = (w * NKP + n) * CK;
    #pragma unroll
    for (int c = 0; c < CK; c++) g_A[base + c] = __float2half(v[c] * inv);
}

// ---------------------------------------------------------------- src prep (low-reg, smem-staged)
#define PSTR 66                                    // floats per pixel row in smem
__global__ __launch_bounds__(128) void k_prep_src(const float* __restrict__ dd, int blk0) {
    __shared__ float sv[128 * PSTR];               // [px][c], 33.8 KB
    __shared__ float sinv[128];
    int bid = blockIdx.x + blk0;
    int tid = threadIdx.x;
    int b = bid >> 9;                              // 512 blocks per frame
    int m0 = (bid * 128) & (HW - 1);
    const float* src = dd + (size_t)(b * 4) * CK * HW + m0;

    // phase 1: coalesced plane loads; ss in the same c-order as R11 (bit-identical)
    float ss = 0.f;
    float* myrow = sv + tid * PSTR;
    #pragma unroll
    for (int c = 0; c < CK; c++) {
        float x = src[(size_t)c * HW + tid];
        ss += x * x;
        myrow[c] = x;
    }
    sinv[tid] = 1.f / fmaxf(sqrtf(ss), 1e-12f);
    __syncthreads();

    // phase 2: identical output packing/order as R11's prep
    uint32_t* oH = reinterpret_cast<uint32_t*>(g_B) + (size_t)bid * 128 * 32;
    #pragma unroll
    for (int i = 0; i < 32; i++) {
        int u = tid + i * 128;
        int mm = u >> 5, j = u & 31;
        float inv = sinv[mm];
        float2 xy = *reinterpret_cast<const float2*>(sv + mm * PSTR + 2 * j);
        __half h0 = __float2half(xy.x * inv);
        __half h1 = __float2half(xy.y * inv);
        oH[u] = (uint32_t)__half_as_ushort(h0) | ((uint32_t)__half_as_ushort(h1) << 16);
    }
}

// ---------------------------------------------------------------- persistent GEMM + softmax (R11 verbatim)
#define SM_A 0
#define SM_B(half, buf) (16384 + (half) * 16384 + (buf) * 8192)
#define SM_TOT 49152

__global__ void __launch_bounds__(256, 2) k_gemm() {
    extern __shared__ char smem[];
    uint32_t sb = smem_u32(smem);
    int tid = threadIdx.x;
    int cta = blockIdx.x;
    int grp = cta % NGRP, j = cta / NGRP;
    int w = grp >> 1, kh = grp & 1, b = w / 3;
    int t0 = (j * NTILE) / CPG, t1 = ((j + 1) * NTILE) / CPG;

    int lane = tid & 31, wid = tid >> 5;
    int half = tid >> 7;
    int h = tid & 127;
    int n0 = half * 64;
    int barid = 1 + half;

    {
        const __half* gA = g_A + (size_t)(w * NKP + kh * 128) * CK;
        #pragma unroll
        for (int i = 0; i < 4; i++) {
            int ch = tid + i * 256;
            int row = ch >> 3, c = ch & 7;
            const __half* src = gA + row * CK + c * 8;
            uint32_t dst = sb + SM_A + row * 128 + (((c ^ (row & 7))) << 4);
            CP16(dst, (const void*)src);
        }
    }
    const __half* gB = g_B + (size_t)b * HW * CK;
    auto prefB = [&](int buf, int t) {
        #pragma unroll
        for (int i = 0; i < 4; i++) {
            int ch = h + i * 128;
            int row = ch >> 3, c = ch & 7;
            const __half* src = gB + (size_t)(t * TPX + n0 + row) * CK + c * 8;
            uint32_t dst = sb + SM_B(half, buf) + row * 128 + (((c ^ (row & 7))) << 4);
            CP16(dst, (const void*)src);
        }
    };
    prefB(0, t0);
    CP_COMMIT();

    int m0 = (wid & 3) * 32;
    int aRow = (lane & 7) + ((lane >> 3) & 1) * 8;
    int aCh  = (lane >> 4) & 1;
    int bRow = (lane & 7) + ((lane >> 4) & 1) * 8;
    int bCh  = (lane >> 3) & 1;
    int rA0 = m0 + aRow, rA1 = rA0 + 16;
    uint32_t aB0 = sb + SM_A + rA0 * 128, aB1 = sb + SM_A + rA1 * 128;
    int xA0 = rA0 & 7, xA1 = rA1 & 7;
    uint32_t bOff[4]; int xB[4];
    #pragma unroll
    for (int q = 0; q < 4; q++) {
        int rB = q * 16 + bRow;
        bOff[q] = rB * 128; xB[q] = rB & 7;
    }
    int g = lane >> 2, t4 = lane & 3;
    const float K1 = 144.2695041f;                 // 100 * log2(e)
    float t4f2 = (float)(n0 + t4 * 2);

    float sA[2][2] = {{0.f,0.f},{0.f,0.f}};
    float uA[2][2] = {{0.f,0.f},{0.f,0.f}};
    float vA[2][2] = {{0.f,0.f},{0.f,0.f}};

    int buf = 0;
    for (int t = t0; t < t1; t++) {
        if (t + 1 < t1) prefB(buf ^ 1, t + 1);
        CP_COMMIT();
        CP_WAIT1();
        if (t == t0) __syncthreads();
        else BARH(barid);

        float acc[2][8][4];
        #pragma unroll
        for (int i = 0; i < 2; i++)
            #pragma unroll
            for (int nt = 0; nt < 8; nt++)
                #pragma unroll
                for (int q = 0; q < 4; q++) acc[i][nt][q] = 0.f;

        uint32_t bB = sb + SM_B(half, buf);
        #pragma unroll
        for (int ks = 0; ks < 4; ks++) {
            uint32_t Af0[4], Af1[4], Bf[4][4];
            int chA = aCh + 2 * ks;
            int chB = bCh + 2 * ks;
            LDSM4(Af0, aB0 + ((chA ^ xA0) << 4));
            LDSM4(Af1, aB1 + ((chA ^ xA1) << 4));
            #pragma unroll
            for (int q = 0; q < 4; q++) LDSM4(Bf[q], bB + bOff[q] + ((chB ^ xB[q]) << 4));
            #pragma unroll
            for (int nt = 0; nt < 8; nt++) {
                uint32_t b0 = Bf[nt >> 1][(nt & 1) * 2];
                uint32_t b1 = Bf[nt >> 1][(nt & 1) * 2 + 1];
                MMA16816(acc[0][nt], Af0, b0, b1);
                MMA16816(acc[1][nt], Af1, b0, b1);
            }
        }

        BARH(barid);

        float uoff = (float)((t & 1) * 128);
        float vt = (float)(t >> 1);
        #pragma unroll
        for (int mt = 0; mt < 2; mt++) {
            float s0 = 0.f, m0f = 0.f, o0 = 0.f;
            float s1 = 0.f, m1f = 0.f, o1 = 0.f;
            #pragma unroll
            for (int nt = 0; nt < 8; nt++) {
                float ntf = (float)nt;
                float e0, e1, e2, e3;
                asm("ex2.approx.ftz.f32 %0, %1;" : "=f"(e0) : "f"(fmaf(acc[mt][nt][0], K1, -K1)));
                asm("ex2.approx.ftz.f32 %0, %1;" : "=f"(e1) : "f"(fmaf(acc[mt][nt][1], K1, -K1)));
                asm("ex2.approx.ftz.f32 %0, %1;" : "=f"(e2) : "f"(fmaf(acc[mt][nt][2], K1, -K1)));
                asm("ex2.approx.ftz.f32 %0, %1;" : "=f"(e3) : "f"(fmaf(acc[mt][nt][3], K1, -K1)));
                float p0 = e0 + e1, p1 = e2 + e3;
                s0 += p0;  m0f = fmaf(ntf, p0, m0f);  o0 += e1;
                s1 += p1;  m1f = fmaf(ntf, p1, m1f);  o1 += e3;
            }
            float u0 = fmaf(8.f, m0f, o0); u0 = fmaf(t4f2 + uoff, s0, u0);
            float u1 = fmaf(8.f, m1f, o1); u1 = fmaf(t4f2 + uoff, s1, u1);
            sA[mt][0] += s0;  uA[mt][0] += u0;  vA[mt][0] = fmaf(vt, s0, vA[mt][0]);
            sA[mt][1] += s1;  uA[mt][1] += u1;  vA[mt][1] = fmaf(vt, s1, vA[mt][1]);
        }
        buf ^= 1;
    }

    #pragma unroll
    for (int mt = 0; mt < 2; mt++) {
        #pragma unroll
        for (int sr = 0; sr < 2; sr++) {
            float s = sA[mt][sr], u = uA[mt][sr], v = vA[mt][sr];
            #pragma unroll
            for (int d = 1; d <= 2; d <<= 1) {
                s += __shfl_xor_sync(0xFFFFFFFF, s, d);
                u += __shfl_xor_sync(0xFFFFFFFF, u, d);
                v += __shfl_xor_sync(0xFFFFFFFF, v, d);
            }
            if (t4 == 0) {
                int r = m0 + mt * 16 + sr * 8 + g;
                size_t row = (size_t)w * NKP + kh * 128 + r;
                g_part[row * NPART + j * 2 + half] = make_float4(s, u, v, 0.f);
            }
        }
    }
}

// ---------------------------------------------------------------- reduce + tail merged (R11 verbatim)
__global__ __launch_bounds__(256) void k_finish(const float* __restrict__ scores,
                                                float* __restrict__ out) {
    if (blockIdx.x < 192) {
        int row = blockIdx.x * 8 + (threadIdx.x >> 5);
        int lane = threadIdx.x & 31;
        const float4* p = g_part + (size_t)row * NPART;
        float s = 0.f, u = 0.f, v = 0.f;
        #pragma unroll
        for (int i = 0; i < 4; i++) {
            int idx = lane + i * 32;
            if (idx < NPART) {
                float4 q = p[idx];
                s += q.x; u += q.y; v += q.z;
            }
        }
        #pragma unroll
        for (int d = 16; d > 0; d >>= 1) {
            s += __shfl_xor_sync(0xFFFFFFFF, s, d);
            u += __shfl_xor_sync(0xFFFFFFFF, u, d);
            v += __shfl_xor_sync(0xFFFFFFFF, v, d);
        }
        if (lane == 0) {
            float inv = 1.f / s;
            out[row * 2 + 0] = u * inv;
            out[row * 2 + 1] = v * inv;
        }
    } else {
        int w = blockIdx.x - 192, n = threadIdx.x;
        int f = (w / 3) * 4 + (w % 3) + 1;
        out[3072 + w * NKP + n] = scores[f * NKP + n];
        if (n == 0) {
            out[4608 + w] = (float)f;
            out[4614 + w] = (float)((w / 3) * 4);
        }
    }
}

extern "C" void kernel_launch(void* const* d_in, const int* in_sizes, int n_in,
                              void* d_out, int out_size) {
    (void)in_sizes; (void)n_in; (void)out_size;
    const float* scores = (const float*)d_in[0];
    const float* kd     = (const float*)d_in[1];
    const float* dd     = (const float*)d_in[2];
    float* out = (float*)d_out;

    cudaFuncSetAttribute(k_gemm, cudaFuncAttributeMaxDynamicSharedMemorySize, SM_TOT);

    k_prep_tgt<<<NGRP, 128>>>(kd);          // launch 0
    k_prep_src<<<512, 128>>>(dd, 0);        // launch 1
    k_prep_src<<<512, 128>>>(dd, 512);      // launch 2
    k_gemm<<<NCTA, 256, SM_TOT>>>();        // launch 3  (ncu lands here)
    k_finish<<<198, 256>>>(scores, out);    // launch 4
}

// round 17
// speedup vs baseline: 1.4790x; 1.1075x over previous
#include <cuda_runtime.h>
#include <cuda_fp16.h>
#include <cstdint>

// SoftmaxRefMatcher: persistent mma.sync fp16 GEMM + fused fixed-shift softmax.
// R16: 3 launches (merged prep). k_gemm = R11 verbatim (proven 46.4-46.9us).
// BW=8, C=64, N=256, HW=65536, WINDOW=4 -> B=2, NW=6, 12 (w,kh) groups.

#define CK     64
#define NKP    256
#define HW     65536
#define NW     6
#define TPX    128
#define NTILE  512
#define NGRP   12
#define CPG    49
#define NCTA   (NGRP * CPG)     // 588
#define NPART  (CPG * 2)

__device__ __align__(256) __half g_A[NW * NKP * CK];
__device__ __align__(256) __half g_B[2 * HW * CK];
__device__ __align__(256) float4 g_part[NW * NKP * NPART];   // {s,u,v,pad}

__device__ __forceinline__ uint32_t smem_u32(const void* p) {
    uint32_t a;
    asm("{ .reg .u64 t; cvta.to.shared.u64 t, %1; cvt.u32.u64 %0, t; }" : "=r"(a) : "l"(p));
    return a;
}
#define LDSM4(R, addr) \
    asm volatile("ldmatrix.sync.aligned.m8n8.x4.shared.b16 {%0,%1,%2,%3}, [%4];" \
        : "=r"((R)[0]), "=r"((R)[1]), "=r"((R)[2]), "=r"((R)[3]) : "r"(addr))
#define MMA16816(D, A, b0, b1) \
    asm volatile("mma.sync.aligned.m16n8k16.row.col.f32.f16.f16.f32 " \
        "{%0,%1,%2,%3}, {%4,%5,%6,%7}, {%8,%9}, {%0,%1,%2,%3};" \
        : "+f"((D)[0]), "+f"((D)[1]), "+f"((D)[2]), "+f"((D)[3]) \
        : "r"((A)[0]), "r"((A)[1]), "r"((A)[2]), "r"((A)[3]), "r"(b0), "r"(b1))
#define CP16(dst, src) \
    asm volatile("cp.async.cg.shared.global [%0], [%1], 16;" :: "r"(dst), "l"(src))
#define CP_COMMIT() asm volatile("cp.async.commit_group;" ::: "memory")
#define CP_WAIT1()  asm volatile("cp.async.wait_group 1;" ::: "memory")
#define BARH(id)    asm volatile("bar.sync %0, 128;" :: "r"(id) : "memory")

// ---------------------------------------------------------------- merged prep (src 0..1023, tgt 1024..1035)
#define PSTR 66
__global__ __launch_bounds__(128) void k_prep(const float* __restrict__ kd,
                                              const float* __restrict__ dd) {
    __shared__ float sv[128 * PSTR];               // used by src path only
    __shared__ float sinv[128];
    int bid = blockIdx.x;
    int tid = threadIdx.x;
    if (bid < 1024) {
        // ---- src path (R15 low-reg, bit-identical output order) ----
        int b = bid >> 9;
        int m0 = (bid * 128) & (HW - 1);
        const float* src = dd + (size_t)(b * 4) * CK * HW + m0;
        float ss = 0.f;
        float* myrow = sv + tid * PSTR;
        #pragma unroll
        for (int c = 0; c < CK; c++) {
            float x = src[(size_t)c * HW + tid];
            ss += x * x;
            myrow[c] = x;
        }
        sinv[tid] = 1.f / fmaxf(sqrtf(ss), 1e-12f);
        __syncthreads();
        uint32_t* oH = reinterpret_cast<uint32_t*>(g_B) + (size_t)bid * 128 * 32;
        #pragma unroll
        for (int i = 0; i < 32; i++) {
            int u = tid + i * 128;
            int mm = u >> 5, j = u & 31;
            float inv = sinv[mm];
            float2 xy = *reinterpret_cast<const float2*>(sv + mm * PSTR + 2 * j);
            __half h0 = __float2half(xy.x * inv);
            __half h1 = __float2half(xy.y * inv);
            oH[u] = (uint32_t)__half_as_ushort(h0) | ((uint32_t)__half_as_ushort(h1) << 16);
        }
    } else {
        // ---- tgt path (R11 verbatim) ----
        int idx = bid - 1024;               // 0..11
        int w = idx >> 1;
        int n = (idx & 1) * 128 + tid;
        int f = (w / 3) * 4 + (w % 3) + 1;
        const float* src = kd + f * CK * NKP + n;
        float v[CK]; float ss = 0.f;
        #pragma unroll
        for (int c = 0; c < CK; c++) { v[c] = src[c * NKP]; ss += v[c] * v[c]; }
        float inv = 1.f / fmaxf(sqrtf(ss), 1e-12f);
        int base = (w * NKP + n) * CK;
        #pragma unroll
        for (int c = 0; c < CK; c++) g_A[base + c] = __float2half(v[c] * inv);
    }
}

// ---------------------------------------------------------------- persistent GEMM + softmax (R11 verbatim)
#define SM_A 0
#define SM_B(half, buf) (16384 + (half) * 16384 + (buf) * 8192)
#define SM_TOT 49152

__global__ void __launch_bounds__(256, 2) k_gemm() {
    extern __shared__ char smem[];
    uint32_t sb = smem_u32(smem);
    int tid = threadIdx.x;
    int cta = blockIdx.x;
    int grp = cta % NGRP, j = cta / NGRP;
    int w = grp >> 1, kh = grp & 1, b = w / 3;
    int t0 = (j * NTILE) / CPG, t1 = ((j + 1) * NTILE) / CPG;

    int lane = tid & 31, wid = tid >> 5;
    int half = tid >> 7;
    int h = tid & 127;
    int n0 = half * 64;
    int barid = 1 + half;

    {
        const __half* gA = g_A + (size_t)(w * NKP + kh * 128) * CK;
        #pragma unroll
        for (int i = 0; i < 4; i++) {
            int ch = tid + i * 256;
            int row = ch >> 3, c = ch & 7;
            const __half* src = gA + row * CK + c * 8;
            uint32_t dst = sb + SM_A + row * 128 + (((c ^ (row & 7))) << 4);
            CP16(dst, (const void*)src);
        }
    }
    const __half* gB = g_B + (size_t)b * HW * CK;
    auto prefB = [&](int buf, int t) {
        #pragma unroll
        for (int i = 0; i < 4; i++) {
            int ch = h + i * 128;
            int row = ch >> 3, c = ch & 7;
            const __half* src = gB + (size_t)(t * TPX + n0 + row) * CK + c * 8;
            uint32_t dst = sb + SM_B(half, buf) + row * 128 + (((c ^ (row & 7))) << 4);
            CP16(dst, (const void*)src);
        }
    };
    prefB(0, t0);
    CP_COMMIT();

    int m0 = (wid & 3) * 32;
    int aRow = (lane & 7) + ((lane >> 3) & 1) * 8;
    int aCh  = (lane >> 4) & 1;
    int bRow = (lane & 7) + ((lane >> 4) & 1) * 8;
    int bCh  = (lane >> 3) & 1;
    int rA0 = m0 + aRow, rA1 = rA0 + 16;
    uint32_t aB0 = sb + SM_A + rA0 * 128, aB1 = sb + SM_A + rA1 * 128;
    int xA0 = rA0 & 7, xA1 = rA1 & 7;
    uint32_t bOff[4]; int xB[4];
    #pragma unroll
    for (int q = 0; q < 4; q++) {
        int rB = q * 16 + bRow;
        bOff[q] = rB * 128; xB[q] = rB & 7;
    }
    int g = lane >> 2, t4 = lane & 3;
    const float K1 = 144.2695041f;                 // 100 * log2(e)
    float t4f2 = (float)(n0 + t4 * 2);

    float sA[2][2] = {{0.f,0.f},{0.f,0.f}};
    float uA[2][2] = {{0.f,0.f},{0.f,0.f}};
    float vA[2][2] = {{0.f,0.f},{0.f,0.f}};

    int buf = 0;
    for (int t = t0; t < t1; t++) {
        if (t + 1 < t1) prefB(buf ^ 1, t + 1);
        CP_COMMIT();
        CP_WAIT1();
        if (t == t0) __syncthreads();
        else BARH(barid);

        float acc[2][8][4];
        #pragma unroll
        for (int i = 0; i < 2; i++)
            #pragma unroll
            for (int nt = 0; nt < 8; nt++)
                #pragma unroll
                for (int q = 0; q < 4; q++) acc[i][nt][q] = 0.f;

        uint32_t bB = sb + SM_B(half, buf);
        #pragma unroll
        for (int ks = 0; ks < 4; ks++) {
            uint32_t Af0[4], Af1[4], Bf[4][4];
            int chA = aCh + 2 * ks;
            int chB = bCh + 2 * ks;
            LDSM4(Af0, aB0 + ((chA ^ xA0) << 4));
            LDSM4(Af1, aB1 + ((chA ^ xA1) << 4));
            #pragma unroll
            for (int q = 0; q < 4; q++) LDSM4(Bf[q], bB + bOff[q] + ((chB ^ xB[q]) << 4));
            #pragma unroll
            for (int nt = 0; nt < 8; nt++) {
                uint32_t b0 = Bf[nt >> 1][(nt & 1) * 2];
                uint32_t b1 = Bf[nt >> 1][(nt & 1) * 2 + 1];
                MMA16816(acc[0][nt], Af0, b0, b1);
                MMA16816(acc[1][nt], Af1, b0, b1);
            }
        }

        BARH(barid);

        float uoff = (float)((t & 1) * 128);
        float vt = (float)(t >> 1);
        #pragma unroll
        for (int mt = 0; mt < 2; mt++) {
            float s0 = 0.f, m0f = 0.f, o0 = 0.f;
            float s1 = 0.f, m1f = 0.f, o1 = 0.f;
            #pragma unroll
            for (int nt = 0; nt < 8; nt++) {
                float ntf = (float)nt;
                float e0, e1, e2, e3;
                asm("ex2.approx.ftz.f32 %0, %1;" : "=f"(e0) : "f"(fmaf(acc[mt][nt][0], K1, -K1)));
                asm("ex2.approx.ftz.f32 %0, %1;" : "=f"(e1) : "f"(fmaf(acc[mt][nt][1], K1, -K1)));
                asm("ex2.approx.ftz.f32 %0, %1;" : "=f"(e2) : "f"(fmaf(acc[mt][nt][2], K1, -K1)));
                asm("ex2.approx.ftz.f32 %0, %1;" : "=f"(e3) : "f"(fmaf(acc[mt][nt][3], K1, -K1)));
                float p0 = e0 + e1, p1 = e2 + e3;
                s0 += p0;  m0f = fmaf(ntf, p0, m0f);  o0 += e1;
                s1 += p1;  m1f = fmaf(ntf, p1, m1f);  o1 += e3;
            }
            float u0 = fmaf(8.f, m0f, o0); u0 = fmaf(t4f2 + uoff, s0, u0);
            float u1 = fmaf(8.f, m1f, o1); u1 = fmaf(t4f2 + uoff, s1, u1);
            sA[mt][0] += s0;  uA[mt][0] += u0;  vA[mt][0] = fmaf(vt, s0, vA[mt][0]);
            sA[mt][1] += s1;  uA[mt][1] += u1;  vA[mt][1] = fmaf(vt, s1, vA[mt][1]);
        }
        buf ^= 1;
    }

    #pragma unroll
    for (int mt = 0; mt < 2; mt++) {
        #pragma unroll
        for (int sr = 0; sr < 2; sr++) {
            float s = sA[mt][sr], u = uA[mt][sr], v = vA[mt][sr];
            #pragma unroll
            for (int d = 1; d <= 2; d <<= 1) {
                s += __shfl_xor_sync(0xFFFFFFFF, s, d);
                u += __shfl_xor_sync(0xFFFFFFFF, u, d);
                v += __shfl_xor_sync(0xFFFFFFFF, v, d);
            }
            if (t4 == 0) {
                int r = m0 + mt * 16 + sr * 8 + g;
                size_t row = (size_t)w * NKP + kh * 128 + r;
                g_part[row * NPART + j * 2 + half] = make_float4(s, u, v, 0.f);
            }
        }
    }
}

// ---------------------------------------------------------------- reduce + tail merged (R11 verbatim)
__global__ __launch_bounds__(256) void k_finish(const float* __restrict__ scores,
                                                float* __restrict__ out) {
    if (blockIdx.x < 192) {
        int row = blockIdx.x * 8 + (threadIdx.x >> 5);
        int lane = threadIdx.x & 31;
        const float4* p = g_part + (size_t)row * NPART;
        float s = 0.f, u = 0.f, v = 0.f;
        #pragma unroll
        for (int i = 0; i < 4; i++) {
            int idx = lane + i * 32;
            if (idx < NPART) {
                float4 q = p[idx];
                s += q.x; u += q.y; v += q.z;
            }
        }
        #pragma unroll
        for (int d = 16; d > 0; d >>= 1) {
            s += __shfl_xor_sync(0xFFFFFFFF, s, d);
            u += __shfl_xor_sync(0xFFFFFFFF, u, d);
            v += __shfl_xor_sync(0xFFFFFFFF, v, d);
        }
        if (lane == 0) {
            float inv = 1.f / s;
            out[row * 2 + 0] = u * inv;
            out[row * 2 + 1] = v * inv;
        }
    } else {
        int w = blockIdx.x - 192, n = threadIdx.x;
        int f = (w / 3) * 4 + (w % 3) + 1;
        out[3072 + w * NKP + n] = scores[f * NKP + n];
        if (n == 0) {
            out[4608 + w] = (float)f;
            out[4614 + w] = (float)((w / 3) * 4);
        }
    }
}

extern "C" void kernel_launch(void* const* d_in, const int* in_sizes, int n_in,
                              void* d_out, int out_size) {
    (void)in_sizes; (void)n_in; (void)out_size;
    const float* scores = (const float*)d_in[0];
    const float* kd     = (const float*)d_in[1];
    const float* dd     = (const float*)d_in[2];
    float* out = (float*)d_out;

    cudaFuncSetAttribute(k_gemm, cudaFuncAttributeMaxDynamicSharedMemorySize, SM_TOT);

    k_prep<<<1036, 128>>>(kd, dd);          // launch 0 (src + tgt merged)
    k_gemm<<<NCTA, 256, SM_TOT>>>();        // launch 1
    k_finish<<<198, 256>>>(scores, out);    // launch 2
}